// round 7
// baseline (speedup 1.0000x reference)
#include <cuda_runtime.h>

#define N_NODES 10000
#define N_EDGES 640000
#define DIM 128
#define CAP 160   // max in-degree bucket capacity (mean 64, sigma 8; 160 ~ 12 sigma)

typedef unsigned long long u64;

// ---------------- scratch (no allocations allowed) ----------------
__device__ int   g_is64;
__device__ int   g_cur [N_NODES];
__device__ int   g_bkt [N_NODES * CAP];
__device__ float g_agg [N_NODES * DIM];
__device__ float g_h1  [N_NODES * DIM];

// Compile-time selector for internal buffers: 0 = external ptr, 1 = g_agg, 2 = g_h1
template <int SEL>
__device__ __forceinline__ const float* sel_ptr(const float* p) {
    if (SEL == 1) return g_agg;
    if (SEL == 2) return g_h1;
    return p;
}

// Read edge index e from the src (half=0) or dst (half=1) row, either dtype.
__device__ __forceinline__ int edge_at(const void* ei, int half, int e, int is64) {
    if (is64) {
        return (int)((const long long*)ei)[(size_t)half * N_EDGES + e];
    } else {
        return ((const int*)ei)[(size_t)half * N_EDGES + e];
    }
}

// ---------------- init: zero counters + dtype detect (fused) ----------------
// int64 node indices (< 2^31) viewed as int32 give [v,0,v,0,...]: odd words all 0.
__global__ void k_init(const int* __restrict__ ei32) {
    int i = blockIdx.x * blockDim.x + threadIdx.x;
    if (i < N_NODES) g_cur[i] = 0;
    if (i == 0) {
        int all_zero = 1;
        for (int j = 1; j < 64; j += 2)
            if (ei32[j] != 0) { all_zero = 0; break; }
        g_is64 = all_zero;
    }
}

// ---------------- single-pass bucket scatter: 4 edges/thread for MLP ----------------
__global__ void k_scatter(const void* __restrict__ ei) {
    int base = blockIdx.x * (blockDim.x * 4) + threadIdx.x;
    int is64 = g_is64;
#pragma unroll
    for (int j = 0; j < 4; j++) {
        int e = base + j * 256;
        if (e < N_EDGES) {
            int src = edge_at(ei, 0, e, is64);
            int dst = edge_at(ei, 1, e, is64);
            int p = atomicAdd(&g_cur[dst], 1);
            g_bkt[dst * CAP + p] = src;
        }
    }
}

// ---------------- mean aggregation: one warp per destination node ----------------
template <int SRC_SEL>
__global__ void k_agg(const float* __restrict__ hx) {
    int node = (blockIdx.x * blockDim.x + threadIdx.x) >> 5;
    int lane = threadIdx.x & 31;
    if (node >= N_NODES) return;
    const float* h = sel_ptr<SRC_SEL>(hx);
    const int* bkt = &g_bkt[node * CAP];
    int cnt = g_cur[node];
    const float4* h4 = (const float4*)h;
    float4 acc = make_float4(0.f, 0.f, 0.f, 0.f);
    int e = 0;
    for (; e + 4 <= cnt; e += 4) {
        int s0 = bkt[e + 0];
        int s1 = bkt[e + 1];
        int s2 = bkt[e + 2];
        int s3 = bkt[e + 3];
        float4 v0 = __ldg(&h4[s0 * 32 + lane]);
        float4 v1 = __ldg(&h4[s1 * 32 + lane]);
        float4 v2 = __ldg(&h4[s2 * 32 + lane]);
        float4 v3 = __ldg(&h4[s3 * 32 + lane]);
        acc.x += (v0.x + v1.x) + (v2.x + v3.x);
        acc.y += (v0.y + v1.y) + (v2.y + v3.y);
        acc.z += (v0.z + v1.z) + (v2.z + v3.z);
        acc.w += (v0.w + v1.w) + (v2.w + v3.w);
    }
    for (; e < cnt; e++) {
        float4 v = __ldg(&h4[bkt[e] * 32 + lane]);
        acc.x += v.x; acc.y += v.y; acc.z += v.z; acc.w += v.w;
    }
    float inv = 1.0f / (float)(cnt > 0 ? cnt : 1);
    ((float4*)g_agg)[node * 32 + lane] =
        make_float4(acc.x * inv, acc.y * inv, acc.z * inv, acc.w * inv);
}

// ---------------- packed-f32x2 helpers ----------------
__device__ __forceinline__ u64 dup2(float v) {
    u64 r;
    asm("mov.b64 %0, {%1, %1};" : "=l"(r) : "f"(v));
    return r;
}
__device__ __forceinline__ void fma2(u64& acc, u64 a, u64 b) {
    asm("fma.rn.f32x2 %0, %1, %2, %0;" : "+l"(acc) : "l"(a), "l"(b));
}
__device__ __forceinline__ void unpack2(u64 v, float& lo, float& hi) {
    asm("mov.b64 {%0, %1}, %2;" : "=f"(lo), "=f"(hi) : "l"(v));
}

// ---------------- fused multi-matrix GEMM (f32x2, BM=32 for occupancy) ----------
// out[m,d] = relu( sum_mat( A_mat[m,:] . W_mat[d,:] ) + b0[d] (+ b1[d]) )
// BM=32 rows per block, 128 output cols, 256 threads -> grid 313 (vs 157 before).
// Per thread: 4 rows x 4 cols as 2 row-pairs (u64 direct from smem, warp-uniform
// broadcast) x 4 cols = 8 FMA2 per (k,mat).
template <int NMAT, bool NB2, int S0, int S1, int S2, bool OUT_H1>
__global__ __launch_bounds__(256)
void k_gemm(const float* __restrict__ A0, const float* __restrict__ W0,
            const float* __restrict__ A1, const float* __restrict__ W1,
            const float* __restrict__ A2, const float* __restrict__ W2,
            const float* __restrict__ b0, const float* __restrict__ b1,
            float* __restrict__ out_ext) {
    constexpr int BM = 32, BK = 16;
    __shared__ float As[NMAT][BK][BM + 4];
    __shared__ float Ws[NMAT][BK][DIM + 4];

    const float* Aarr[3];
    Aarr[0] = sel_ptr<S0>(A0);
    if (NMAT > 1) Aarr[1] = sel_ptr<S1>(A1);
    if (NMAT > 2) Aarr[2] = sel_ptr<S2>(A2);
    const float* Warr[3] = {W0, W1, W2};
    float* out = OUT_H1 ? g_h1 : out_ext;

    const int t = threadIdx.x;
    const int m0 = blockIdx.x * BM;
    const int lm = t >> 2;            // 0..63  (W-stage row; A-stage uses t<128)
    const int kq = (t & 3) * 4;       // 0,4,8,12
    const int tgrp = t >> 5;          // 0..7  -> rows tgrp*4 .. +3
    const int tcol = t & 31;          // 0..31 -> cols tcol*4 .. +3
    const int rowBase = tgrp * 4;
    const int col = tcol * 4;

    u64 acc2[2][4];                   // [row-pair][col]
#pragma unroll
    for (int p = 0; p < 2; p++)
#pragma unroll
        for (int j = 0; j < 4; j++) acc2[p][j] = 0ull;

    for (int kt = 0; kt < DIM / BK; kt++) {
        const int k0 = kt * BK;
#pragma unroll
        for (int mat = 0; mat < NMAT; mat++) {
            // A tile: 32 rows x BK floats, loaded by threads t < 128
            if (t < 128) {
                int arow = t >> 2;            // 0..31
                int grow = m0 + arow;
                float4 va = make_float4(0.f, 0.f, 0.f, 0.f);
                if (grow < N_NODES)
                    va = *(const float4*)&Aarr[mat][grow * DIM + k0 + kq];
                As[mat][kq + 0][arow] = va.x;
                As[mat][kq + 1][arow] = va.y;
                As[mat][kq + 2][arow] = va.z;
                As[mat][kq + 3][arow] = va.w;
            }
            // W tile: 128 cols x BK floats, all 256 threads, 2 rows each
#pragma unroll
            for (int r = 0; r < 2; r++) {
                int d = lm + r * 64;
                float4 vw = *(const float4*)&Warr[mat][d * DIM + k0 + kq];
                Ws[mat][kq + 0][d] = vw.x;
                Ws[mat][kq + 1][d] = vw.y;
                Ws[mat][kq + 2][d] = vw.z;
                Ws[mat][kq + 3][d] = vw.w;
            }
        }
        __syncthreads();
#pragma unroll
        for (int k = 0; k < BK; k++) {
#pragma unroll
            for (int mat = 0; mat < NMAT; mat++) {
                // warp-uniform broadcast loads (all lanes same address)
                const u64* a64 = (const u64*)&As[mat][k][rowBase];
                u64 ap0 = a64[0], ap1 = a64[1];
                float4 w = *(const float4*)&Ws[mat][k][col];
                u64 wd0 = dup2(w.x), wd1 = dup2(w.y), wd2 = dup2(w.z), wd3 = dup2(w.w);
                fma2(acc2[0][0], ap0, wd0);
                fma2(acc2[1][0], ap1, wd0);
                fma2(acc2[0][1], ap0, wd1);
                fma2(acc2[1][1], ap1, wd1);
                fma2(acc2[0][2], ap0, wd2);
                fma2(acc2[1][2], ap1, wd2);
                fma2(acc2[0][3], ap0, wd3);
                fma2(acc2[1][3], ap1, wd3);
            }
        }
        __syncthreads();
    }

    float bb[4];
#pragma unroll
    for (int j = 0; j < 4; j++) {
        bb[j] = b0[col + j];
        if (NB2) bb[j] += b1[col + j];
    }
#pragma unroll
    for (int p = 0; p < 2; p++) {
        float lo[4], hi[4];
#pragma unroll
        for (int j = 0; j < 4; j++) unpack2(acc2[p][j], lo[j], hi[j]);
        int r0 = m0 + rowBase + 2 * p;
        int r1 = r0 + 1;
        if (r0 < N_NODES) {
            float4 o;
            o.x = fmaxf(lo[0] + bb[0], 0.f);
            o.y = fmaxf(lo[1] + bb[1], 0.f);
            o.z = fmaxf(lo[2] + bb[2], 0.f);
            o.w = fmaxf(lo[3] + bb[3], 0.f);
            *(float4*)&out[r0 * DIM + col] = o;
        }
        if (r1 < N_NODES) {
            float4 o;
            o.x = fmaxf(hi[0] + bb[0], 0.f);
            o.y = fmaxf(hi[1] + bb[1], 0.f);
            o.z = fmaxf(hi[2] + bb[2], 0.f);
            o.w = fmaxf(hi[3] + bb[3], 0.f);
            *(float4*)&out[r1 * DIM + col] = o;
        }
    }
}

// ---------------- launch: kernel launches ONLY, no other CUDA APIs ----------------
extern "C" void kernel_launch(void* const* d_in, const int* in_sizes, int n_in,
                              void* d_out, int out_size) {
    const float* x    = (const float*)d_in[0];
    const void*  ei   = d_in[1];                 // int32 or int64, detected on device
    const float* fc_w = (const float*)d_in[2];
    const float* fc_b = (const float*)d_in[3];
    const float* f_lw = (const float*)d_in[4];
    const float* f_lb = (const float*)d_in[5];
    const float* f_rw = (const float*)d_in[6];
    const float* n_lw = (const float*)d_in[7];
    const float* n_lb = (const float*)d_in[8];
    const float* n_rw = (const float*)d_in[9];
    float* out = (float*)d_out;

    const int TB = 256;
    const int gemm_blocks = (N_NODES + 31) / 32;
    const int agg_blocks = (N_NODES * 32 + TB - 1) / TB;
    const int scat_blocks = (N_EDGES + TB * 4 - 1) / (TB * 4);

    // bucket CSR build (single pass, no count/scan)
    k_init<<<(N_NODES + TB - 1) / TB, TB>>>((const int*)ei);
    k_scatter<<<scat_blocks, TB>>>(ei);

    // conv1: g_h1 = relu(mean_agg(x) @ f_lw^T + f_lb + x @ f_rw^T)
    k_agg<0><<<agg_blocks, TB>>>(x);
    k_gemm<2, false, 1, 0, 0, true><<<gemm_blocks, TB>>>(
        nullptr, f_lw, x, f_rw, nullptr, nullptr, f_lb, nullptr, nullptr);

    // conv2 + fc residual, fused:
    // out = relu(mean_agg(g_h1) @ n_lw^T + n_lb + g_h1 @ n_rw^T + x @ fc_w^T + fc_b)
    k_agg<2><<<agg_blocks, TB>>>(nullptr);
    k_gemm<3, true, 1, 2, 0, false><<<gemm_blocks, TB>>>(
        nullptr, n_lw, nullptr, n_rw, x, fc_w, n_lb, fc_b, out);
}

// round 8
// speedup vs baseline: 1.0283x; 1.0283x over previous
#include <cuda_runtime.h>

#define N_NODES 10000
#define N_EDGES 640000
#define DIM 128
#define CAP 160   // max in-degree bucket capacity (mean 64, sigma 8; 160 ~ 12 sigma)

typedef unsigned long long u64;

// ---------------- scratch (no allocations allowed) ----------------
__device__ int   g_is64;
__device__ int   g_cur [N_NODES];
__device__ int   g_bkt [N_NODES * CAP];
__device__ float g_agg [N_NODES * DIM];
__device__ float g_h1  [N_NODES * DIM];

// Compile-time selector for internal buffers: 0 = external ptr, 1 = g_agg, 2 = g_h1
template <int SEL>
__device__ __forceinline__ const float* sel_ptr(const float* p) {
    if (SEL == 1) return g_agg;
    if (SEL == 2) return g_h1;
    return p;
}

// Read edge index e from the src (half=0) or dst (half=1) row, either dtype.
__device__ __forceinline__ int edge_at(const void* ei, int half, int e, int is64) {
    if (is64) {
        return (int)((const long long*)ei)[(size_t)half * N_EDGES + e];
    } else {
        return ((const int*)ei)[(size_t)half * N_EDGES + e];
    }
}

// ---------------- init: zero counters + dtype detect (fused) ----------------
// int64 node indices (< 2^31) viewed as int32 give [v,0,v,0,...]: odd words all 0.
__global__ void k_init(const int* __restrict__ ei32) {
    int i = blockIdx.x * blockDim.x + threadIdx.x;
    if (i < N_NODES) g_cur[i] = 0;
    if (i == 0) {
        int all_zero = 1;
        for (int j = 1; j < 64; j += 2)
            if (ei32[j] != 0) { all_zero = 0; break; }
        g_is64 = all_zero;
    }
}

// ---------------- single-pass bucket scatter: 4 edges/thread for MLP ----------------
__global__ void k_scatter(const void* __restrict__ ei) {
    int base = blockIdx.x * (blockDim.x * 4) + threadIdx.x;
    int is64 = g_is64;
#pragma unroll
    for (int j = 0; j < 4; j++) {
        int e = base + j * 256;
        if (e < N_EDGES) {
            int src = edge_at(ei, 0, e, is64);
            int dst = edge_at(ei, 1, e, is64);
            int p = atomicAdd(&g_cur[dst], 1);
            g_bkt[dst * CAP + p] = src;
        }
    }
}

// ---------------- mean aggregation: one warp per destination node ----------------
template <int SRC_SEL>
__global__ void k_agg(const float* __restrict__ hx) {
    int node = (blockIdx.x * blockDim.x + threadIdx.x) >> 5;
    int lane = threadIdx.x & 31;
    if (node >= N_NODES) return;
    const float* h = sel_ptr<SRC_SEL>(hx);
    const int* bkt = &g_bkt[node * CAP];
    int cnt = g_cur[node];
    const float4* h4 = (const float4*)h;
    float4 acc = make_float4(0.f, 0.f, 0.f, 0.f);
    int e = 0;
    for (; e + 4 <= cnt; e += 4) {
        int s0 = bkt[e + 0];
        int s1 = bkt[e + 1];
        int s2 = bkt[e + 2];
        int s3 = bkt[e + 3];
        float4 v0 = __ldg(&h4[s0 * 32 + lane]);
        float4 v1 = __ldg(&h4[s1 * 32 + lane]);
        float4 v2 = __ldg(&h4[s2 * 32 + lane]);
        float4 v3 = __ldg(&h4[s3 * 32 + lane]);
        acc.x += (v0.x + v1.x) + (v2.x + v3.x);
        acc.y += (v0.y + v1.y) + (v2.y + v3.y);
        acc.z += (v0.z + v1.z) + (v2.z + v3.z);
        acc.w += (v0.w + v1.w) + (v2.w + v3.w);
    }
    for (; e < cnt; e++) {
        float4 v = __ldg(&h4[bkt[e] * 32 + lane]);
        acc.x += v.x; acc.y += v.y; acc.z += v.z; acc.w += v.w;
    }
    float inv = 1.0f / (float)(cnt > 0 ? cnt : 1);
    ((float4*)g_agg)[node * 32 + lane] =
        make_float4(acc.x * inv, acc.y * inv, acc.z * inv, acc.w * inv);
}

// ---------------- packed-f32x2 helpers ----------------
__device__ __forceinline__ u64 dup2(float v) {
    u64 r;
    asm("mov.b64 %0, {%1, %1};" : "=l"(r) : "f"(v));
    return r;
}
__device__ __forceinline__ void fma2(u64& acc, u64 a, u64 b) {
    asm("fma.rn.f32x2 %0, %1, %2, %0;" : "+l"(acc) : "l"(a), "l"(b));
}
__device__ __forceinline__ void unpack2(u64 v, float& lo, float& hi) {
    asm("mov.b64 {%0, %1}, %2;" : "=f"(lo), "=f"(hi) : "l"(v));
}

// ---------------- fused multi-matrix GEMM (f32x2, tall 16x4 thread tile) -------
// out[m,d] = relu( sum_mat( A_mat[m,:] . W_mat[d,:] ) + b0[d] (+ b1[d]) )
// BM=64 rows x 128 cols per block, 128 threads (4 warps).
// Warp w owns rows w*16..w*16+15; lane owns cols lane*4..+3.
// Per (k,mat): 8 broadcast LDS.64 (A pairs) + 1 LDS.128 (W) + 32 FFMA2
//   -> 2048 FLOP per 512 smem bytes: FMA-pipe-bound, not crossbar-bound.
template <int NMAT, bool NB2, int S0, int S1, int S2, bool OUT_H1>
__global__ __launch_bounds__(128)
void k_gemm(const float* __restrict__ A0, const float* __restrict__ W0,
            const float* __restrict__ A1, const float* __restrict__ W1,
            const float* __restrict__ A2, const float* __restrict__ W2,
            const float* __restrict__ b0, const float* __restrict__ b1,
            float* __restrict__ out_ext) {
    constexpr int BM = 64, BK = 16;
    __shared__ __align__(16) float As[NMAT][BK][BM + 4];
    __shared__ __align__(16) float Ws[NMAT][BK][DIM + 4];

    const float* Aarr[3];
    Aarr[0] = sel_ptr<S0>(A0);
    if (NMAT > 1) Aarr[1] = sel_ptr<S1>(A1);
    if (NMAT > 2) Aarr[2] = sel_ptr<S2>(A2);
    const float* Warr[3] = {W0, W1, W2};
    float* out = OUT_H1 ? g_h1 : out_ext;

    const int t = threadIdx.x;            // 0..127
    const int m0 = blockIdx.x * BM;
    const int q  = t >> 2;                // 0..31
    const int kq = (t & 3) * 4;           // 0,4,8,12
    const int warp = t >> 5;              // 0..3
    const int lane = t & 31;
    const int rowBase = warp * 16;        // warp rows
    const int col = lane * 4;             // lane cols

    u64 acc2[8][4];                       // [row-pair][col]
#pragma unroll
    for (int p = 0; p < 8; p++)
#pragma unroll
        for (int j = 0; j < 4; j++) acc2[p][j] = 0ull;

    for (int kt = 0; kt < DIM / BK; kt++) {
        const int k0 = kt * BK;
#pragma unroll
        for (int mat = 0; mat < NMAT; mat++) {
            // A tile: 64 rows x BK. Each thread loads rows q and q+32 (one float4 each).
#pragma unroll
            for (int r = 0; r < 2; r++) {
                int arow = q + r * 32;
                int grow = m0 + arow;
                float4 va = make_float4(0.f, 0.f, 0.f, 0.f);
                if (grow < N_NODES)
                    va = *(const float4*)&Aarr[mat][grow * DIM + k0 + kq];
                As[mat][kq + 0][arow] = va.x;
                As[mat][kq + 1][arow] = va.y;
                As[mat][kq + 2][arow] = va.z;
                As[mat][kq + 3][arow] = va.w;
            }
            // W tile: 128 cols x BK. Each thread loads 4 d-rows (one float4 each).
#pragma unroll
            for (int r = 0; r < 4; r++) {
                int d = q + r * 32;
                float4 vw = *(const float4*)&Warr[mat][d * DIM + k0 + kq];
                Ws[mat][kq + 0][d] = vw.x;
                Ws[mat][kq + 1][d] = vw.y;
                Ws[mat][kq + 2][d] = vw.z;
                Ws[mat][kq + 3][d] = vw.w;
            }
        }
        __syncthreads();
#pragma unroll
        for (int k = 0; k < BK; k++) {
#pragma unroll
            for (int mat = 0; mat < NMAT; mat++) {
                // 8 warp-uniform broadcast u64 loads: rows rowBase..rowBase+15 as pairs
                const u64* a64 = (const u64*)&As[mat][k][rowBase];
                u64 ap[8];
#pragma unroll
                for (int i = 0; i < 8; i++) ap[i] = a64[i];
                float4 w = *(const float4*)&Ws[mat][k][col];
                u64 wd0 = dup2(w.x), wd1 = dup2(w.y), wd2 = dup2(w.z), wd3 = dup2(w.w);
#pragma unroll
                for (int i = 0; i < 8; i++) {
                    fma2(acc2[i][0], ap[i], wd0);
                    fma2(acc2[i][1], ap[i], wd1);
                    fma2(acc2[i][2], ap[i], wd2);
                    fma2(acc2[i][3], ap[i], wd3);
                }
            }
        }
        __syncthreads();
    }

    float bb[4];
#pragma unroll
    for (int j = 0; j < 4; j++) {
        bb[j] = b0[col + j];
        if (NB2) bb[j] += b1[col + j];
    }
#pragma unroll
    for (int p = 0; p < 8; p++) {
        float lo[4], hi[4];
#pragma unroll
        for (int j = 0; j < 4; j++) unpack2(acc2[p][j], lo[j], hi[j]);
        int r0 = m0 + rowBase + 2 * p;
        int r1 = r0 + 1;
        if (r0 < N_NODES) {
            float4 o;
            o.x = fmaxf(lo[0] + bb[0], 0.f);
            o.y = fmaxf(lo[1] + bb[1], 0.f);
            o.z = fmaxf(lo[2] + bb[2], 0.f);
            o.w = fmaxf(lo[3] + bb[3], 0.f);
            *(float4*)&out[r0 * DIM + col] = o;
        }
        if (r1 < N_NODES) {
            float4 o;
            o.x = fmaxf(hi[0] + bb[0], 0.f);
            o.y = fmaxf(hi[1] + bb[1], 0.f);
            o.z = fmaxf(hi[2] + bb[2], 0.f);
            o.w = fmaxf(hi[3] + bb[3], 0.f);
            *(float4*)&out[r1 * DIM + col] = o;
        }
    }
}

// ---------------- launch: kernel launches ONLY, no other CUDA APIs ----------------
extern "C" void kernel_launch(void* const* d_in, const int* in_sizes, int n_in,
                              void* d_out, int out_size) {
    const float* x    = (const float*)d_in[0];
    const void*  ei   = d_in[1];                 // int32 or int64, detected on device
    const float* fc_w = (const float*)d_in[2];
    const float* fc_b = (const float*)d_in[3];
    const float* f_lw = (const float*)d_in[4];
    const float* f_lb = (const float*)d_in[5];
    const float* f_rw = (const float*)d_in[6];
    const float* n_lw = (const float*)d_in[7];
    const float* n_lb = (const float*)d_in[8];
    const float* n_rw = (const float*)d_in[9];
    float* out = (float*)d_out;

    const int TB = 256;
    const int gemm_blocks = (N_NODES + 63) / 64;
    const int agg_blocks = (N_NODES * 32 + TB - 1) / TB;
    const int scat_blocks = (N_EDGES + TB * 4 - 1) / (TB * 4);

    // bucket CSR build (single pass, no count/scan)
    k_init<<<(N_NODES + TB - 1) / TB, TB>>>((const int*)ei);
    k_scatter<<<scat_blocks, TB>>>(ei);

    // conv1: g_h1 = relu(mean_agg(x) @ f_lw^T + f_lb + x @ f_rw^T)
    k_agg<0><<<agg_blocks, TB>>>(x);
    k_gemm<2, false, 1, 0, 0, true><<<gemm_blocks, 128>>>(
        nullptr, f_lw, x, f_rw, nullptr, nullptr, f_lb, nullptr, nullptr);

    // conv2 + fc residual, fused:
    // out = relu(mean_agg(g_h1) @ n_lw^T + n_lb + g_h1 @ n_rw^T + x @ fc_w^T + fc_b)
    k_agg<2><<<agg_blocks, TB>>>(nullptr);
    k_gemm<3, true, 1, 2, 0, false><<<gemm_blocks, 128>>>(
        nullptr, n_lw, nullptr, n_rw, x, fc_w, n_lb, fc_b, out);
}

// round 9
// speedup vs baseline: 1.0785x; 1.0488x over previous
#include <cuda_runtime.h>

#define N_NODES 10000
#define N_EDGES 640000
#define DIM 128
#define CAP 160   // max in-degree bucket capacity (mean 64, sigma 8; 160 ~ 12 sigma)

typedef unsigned long long u64;

// ---------------- scratch (no allocations allowed) ----------------
__device__ int   g_is64;
__device__ int   g_cur [N_NODES];
__device__ int   g_bkt [N_NODES * CAP];
__device__ float g_agg [N_NODES * DIM];
__device__ float g_h1  [N_NODES * DIM];

// Compile-time selector for internal buffers: 0 = external ptr, 1 = g_agg, 2 = g_h1
template <int SEL>
__device__ __forceinline__ const float* sel_ptr(const float* p) {
    if (SEL == 1) return g_agg;
    if (SEL == 2) return g_h1;
    return p;
}

// Read edge index e from the src (half=0) or dst (half=1) row, either dtype.
__device__ __forceinline__ int edge_at(const void* ei, int half, int e, int is64) {
    if (is64) {
        return (int)((const long long*)ei)[(size_t)half * N_EDGES + e];
    } else {
        return ((const int*)ei)[(size_t)half * N_EDGES + e];
    }
}

// ---------------- init: zero counters + dtype detect (fused) ----------------
// int64 node indices (< 2^31) viewed as int32 give [v,0,v,0,...]: odd words all 0.
__global__ void k_init(const int* __restrict__ ei32) {
    int i = blockIdx.x * blockDim.x + threadIdx.x;
    if (i < N_NODES) g_cur[i] = 0;
    if (i == 0) {
        int all_zero = 1;
        for (int j = 1; j < 64; j += 2)
            if (ei32[j] != 0) { all_zero = 0; break; }
        g_is64 = all_zero;
    }
}

// ---------------- single-pass bucket scatter: 4 edges/thread for MLP ----------------
__global__ void k_scatter(const void* __restrict__ ei) {
    int base = blockIdx.x * (blockDim.x * 4) + threadIdx.x;
    int is64 = g_is64;
#pragma unroll
    for (int j = 0; j < 4; j++) {
        int e = base + j * 256;
        if (e < N_EDGES) {
            int src = edge_at(ei, 0, e, is64);
            int dst = edge_at(ei, 1, e, is64);
            int p = atomicAdd(&g_cur[dst], 1);
            g_bkt[dst * CAP + p] = src;
        }
    }
}

// ---------------- mean aggregation: one warp per destination node ----------------
template <int SRC_SEL>
__global__ void k_agg(const float* __restrict__ hx) {
    int node = (blockIdx.x * blockDim.x + threadIdx.x) >> 5;
    int lane = threadIdx.x & 31;
    if (node >= N_NODES) return;
    const float* h = sel_ptr<SRC_SEL>(hx);
    const int* bkt = &g_bkt[node * CAP];
    int cnt = g_cur[node];
    const float4* h4 = (const float4*)h;
    float4 acc = make_float4(0.f, 0.f, 0.f, 0.f);
    int e = 0;
    for (; e + 4 <= cnt; e += 4) {
        int s0 = bkt[e + 0];
        int s1 = bkt[e + 1];
        int s2 = bkt[e + 2];
        int s3 = bkt[e + 3];
        float4 v0 = __ldg(&h4[s0 * 32 + lane]);
        float4 v1 = __ldg(&h4[s1 * 32 + lane]);
        float4 v2 = __ldg(&h4[s2 * 32 + lane]);
        float4 v3 = __ldg(&h4[s3 * 32 + lane]);
        acc.x += (v0.x + v1.x) + (v2.x + v3.x);
        acc.y += (v0.y + v1.y) + (v2.y + v3.y);
        acc.z += (v0.z + v1.z) + (v2.z + v3.z);
        acc.w += (v0.w + v1.w) + (v2.w + v3.w);
    }
    for (; e < cnt; e++) {
        float4 v = __ldg(&h4[bkt[e] * 32 + lane]);
        acc.x += v.x; acc.y += v.y; acc.z += v.z; acc.w += v.w;
    }
    float inv = 1.0f / (float)(cnt > 0 ? cnt : 1);
    ((float4*)g_agg)[node * 32 + lane] =
        make_float4(acc.x * inv, acc.y * inv, acc.z * inv, acc.w * inv);
}

// ---------------- packed-f32x2 helpers ----------------
__device__ __forceinline__ u64 dup2(float v) {
    u64 r;
    asm("mov.b64 %0, {%1, %1};" : "=l"(r) : "f"(v));
    return r;
}
__device__ __forceinline__ void fma2(u64& acc, u64 a, u64 b) {
    asm("fma.rn.f32x2 %0, %1, %2, %0;" : "+l"(acc) : "l"(a), "l"(b));
}
__device__ __forceinline__ void unpack2(u64 v, float& lo, float& hi) {
    asm("mov.b64 {%0, %1}, %2;" : "=f"(lo), "=f"(hi) : "l"(v));
}

// ---------------- fused multi-matrix GEMM (f32x2, grid-split for occupancy) ----
// out[m,d] = relu( sum_mat( A_mat[m,:] . W_mat[d,:] ) + b0[d] (+ b1[d]) )
// BM=32 rows x BN=64 cols per block, 128 threads (4 warps), grid 313x2 = 626.
// Warp w owns rows w*8..w*8+7 (4 packed pairs, warp-uniform broadcast loads);
// lane owns 2 cols. 8 FMA2 per (k,mat) against 256 B/warp W traffic = 4 FLOP/B.
template <int NMAT, bool NB2, int S0, int S1, int S2, bool OUT_H1>
__global__ __launch_bounds__(128)
void k_gemm(const float* __restrict__ A0, const float* __restrict__ W0,
            const float* __restrict__ A1, const float* __restrict__ W1,
            const float* __restrict__ A2, const float* __restrict__ W2,
            const float* __restrict__ b0, const float* __restrict__ b1,
            float* __restrict__ out_ext) {
    constexpr int BM = 32, BN = 64, BK = 16;
    __shared__ __align__(16) float As[NMAT][BK][BM + 4];
    __shared__ __align__(16) float Ws[NMAT][BK][BN + 4];

    const float* Aarr[3];
    Aarr[0] = sel_ptr<S0>(A0);
    if (NMAT > 1) Aarr[1] = sel_ptr<S1>(A1);
    if (NMAT > 2) Aarr[2] = sel_ptr<S2>(A2);
    const float* Warr[3] = {W0, W1, W2};
    float* out = OUT_H1 ? g_h1 : out_ext;

    const int t = threadIdx.x;            // 0..127
    const int m0 = blockIdx.x * BM;
    const int n0 = blockIdx.y * BN;
    const int q  = t >> 2;                // 0..31
    const int kq = (t & 3) * 4;           // 0,4,8,12
    const int warp = t >> 5;              // 0..3
    const int lane = t & 31;
    const int rowBase = warp * 8;         // warp rows (8)
    const int col = lane * 2;             // lane cols (2), local to tile

    u64 acc2[4][2];                       // [row-pair][col]
#pragma unroll
    for (int p = 0; p < 4; p++)
#pragma unroll
        for (int j = 0; j < 2; j++) acc2[p][j] = 0ull;

    for (int kt = 0; kt < DIM / BK; kt++) {
        const int k0 = kt * BK;
#pragma unroll
        for (int mat = 0; mat < NMAT; mat++) {
            // A tile: 32 rows x BK; one float4 per thread.
            {
                int grow = m0 + q;
                float4 va = make_float4(0.f, 0.f, 0.f, 0.f);
                if (grow < N_NODES)
                    va = *(const float4*)&Aarr[mat][grow * DIM + k0 + kq];
                As[mat][kq + 0][q] = va.x;
                As[mat][kq + 1][q] = va.y;
                As[mat][kq + 2][q] = va.z;
                As[mat][kq + 3][q] = va.w;
            }
            // W tile: 64 cols x BK; two float4 per thread.
#pragma unroll
            for (int r = 0; r < 2; r++) {
                int d = q + r * 32;                       // local col 0..63
                float4 vw = *(const float4*)&Warr[mat][(n0 + d) * DIM + k0 + kq];
                Ws[mat][kq + 0][d] = vw.x;
                Ws[mat][kq + 1][d] = vw.y;
                Ws[mat][kq + 2][d] = vw.z;
                Ws[mat][kq + 3][d] = vw.w;
            }
        }
        __syncthreads();
#pragma unroll
        for (int k = 0; k < BK; k++) {
#pragma unroll
            for (int mat = 0; mat < NMAT; mat++) {
                // 4 warp-uniform broadcast u64 loads: rows rowBase..+7 as pairs
                const u64* a64 = (const u64*)&As[mat][k][rowBase];
                u64 ap0 = a64[0], ap1 = a64[1], ap2 = a64[2], ap3 = a64[3];
                float2 wv = *(const float2*)&Ws[mat][k][col];
                u64 wd0 = dup2(wv.x), wd1 = dup2(wv.y);
                fma2(acc2[0][0], ap0, wd0);
                fma2(acc2[1][0], ap1, wd0);
                fma2(acc2[2][0], ap2, wd0);
                fma2(acc2[3][0], ap3, wd0);
                fma2(acc2[0][1], ap0, wd1);
                fma2(acc2[1][1], ap1, wd1);
                fma2(acc2[2][1], ap2, wd1);
                fma2(acc2[3][1], ap3, wd1);
            }
        }
        __syncthreads();
    }

    float bb[2];
#pragma unroll
    for (int j = 0; j < 2; j++) {
        bb[j] = b0[n0 + col + j];
        if (NB2) bb[j] += b1[n0 + col + j];
    }
#pragma unroll
    for (int p = 0; p < 4; p++) {
        float lo0, hi0, lo1, hi1;
        unpack2(acc2[p][0], lo0, hi0);
        unpack2(acc2[p][1], lo1, hi1);
        int r0 = m0 + rowBase + 2 * p;
        int r1 = r0 + 1;
        if (r0 < N_NODES) {
            float2 o;
            o.x = fmaxf(lo0 + bb[0], 0.f);
            o.y = fmaxf(lo1 + bb[1], 0.f);
            *(float2*)&out[r0 * DIM + n0 + col] = o;
        }
        if (r1 < N_NODES) {
            float2 o;
            o.x = fmaxf(hi0 + bb[0], 0.f);
            o.y = fmaxf(hi1 + bb[1], 0.f);
            *(float2*)&out[r1 * DIM + n0 + col] = o;
        }
    }
}

// ---------------- launch: kernel launches ONLY, no other CUDA APIs ----------------
extern "C" void kernel_launch(void* const* d_in, const int* in_sizes, int n_in,
                              void* d_out, int out_size) {
    const float* x    = (const float*)d_in[0];
    const void*  ei   = d_in[1];                 // int32 or int64, detected on device
    const float* fc_w = (const float*)d_in[2];
    const float* fc_b = (const float*)d_in[3];
    const float* f_lw = (const float*)d_in[4];
    const float* f_lb = (const float*)d_in[5];
    const float* f_rw = (const float*)d_in[6];
    const float* n_lw = (const float*)d_in[7];
    const float* n_lb = (const float*)d_in[8];
    const float* n_rw = (const float*)d_in[9];
    float* out = (float*)d_out;

    const int TB = 256;
    const dim3 gemm_grid((N_NODES + 31) / 32, 2);
    const int agg_blocks = (N_NODES * 32 + TB - 1) / TB;
    const int scat_blocks = (N_EDGES + TB * 4 - 1) / (TB * 4);

    // bucket CSR build (single pass, no count/scan)
    k_init<<<(N_NODES + TB - 1) / TB, TB>>>((const int*)ei);
    k_scatter<<<scat_blocks, TB>>>(ei);

    // conv1: g_h1 = relu(mean_agg(x) @ f_lw^T + f_lb + x @ f_rw^T)
    k_agg<0><<<agg_blocks, TB>>>(x);
    k_gemm<2, false, 1, 0, 0, true><<<gemm_grid, 128>>>(
        nullptr, f_lw, x, f_rw, nullptr, nullptr, f_lb, nullptr, nullptr);

    // conv2 + fc residual, fused:
    // out = relu(mean_agg(g_h1) @ n_lw^T + n_lb + g_h1 @ n_rw^T + x @ fc_w^T + fc_b)
    k_agg<2><<<agg_blocks, TB>>>(nullptr);
    k_gemm<3, true, 1, 2, 0, false><<<gemm_grid, 128>>>(
        nullptr, n_lw, nullptr, n_rw, x, fc_w, n_lb, fc_b, out);
}